// round 4
// baseline (speedup 1.0000x reference)
#include <cuda_runtime.h>

#define B_ 32
#define S_ 2048
#define K_ 512
#define V_ 512
#define H_ 256
#define NSPLIT 16

// Scratch (allocation-free contract: __device__ globals)
__device__ float g_WkT[K_ * H_];            // Wk transposed to k-major [K, H]
__device__ float g_c[B_ * H_];              // bk + bq + q@Wq.T  per (b,h)
__device__ float g_logit[B_ * S_];          // raw logits, then exp() in-place
__device__ float g_part[B_ * NSPLIT * V_];  // partial weighted sums

// ---------- packed f32x2 helpers (FFMA2 is PTX-only; ptxas won't auto-fuse) ----------
static __device__ __forceinline__ unsigned long long pack2(float x, float y) {
    unsigned long long r;
    asm("mov.b64 %0, {%1, %2};" : "=l"(r) : "f"(x), "f"(y));
    return r;
}
static __device__ __forceinline__ unsigned long long fma2(unsigned long long a,
                                                          unsigned long long b,
                                                          unsigned long long c) {
    unsigned long long d;
    asm("fma.rn.f32x2 %0, %1, %2, %3;" : "=l"(d) : "l"(a), "l"(b), "l"(c));
    return d;
}
static __device__ __forceinline__ float2 unpack2(unsigned long long v) {
    float2 f;
    asm("mov.b64 {%0, %1}, %2;" : "=f"(f.x), "=f"(f.y) : "l"(v));
    return f;
}

// ---------- 0. transpose Wk [H,K] -> g_WkT [K,H] (tiny, one-shot per launch) ----------
__global__ void transpose_wk(const float* __restrict__ Wk) {
    int idx = blockIdx.x * blockDim.x + threadIdx.x;
    if (idx < K_ * H_) {
        int kpos = idx / H_;
        int h    = idx % H_;
        g_WkT[idx] = Wk[h * K_ + kpos];
    }
}

// ---------- 1. c[b,h] = bk[h] + bq[h] + sum_k q[b,k] * Wq[h,k] ----------
__global__ void hq_kernel(const float* __restrict__ q, const float* __restrict__ Wq,
                          const float* __restrict__ bq, const float* __restrict__ bk) {
    __shared__ float sq[K_];
    int b = blockIdx.x, h = threadIdx.x;
    for (int i = h; i < K_; i += H_) sq[i] = q[b * K_ + i];
    __syncthreads();
    const float* w = Wq + h * K_;
    float acc = 0.f;
#pragma unroll 8
    for (int kk = 0; kk < K_; kk++) acc = fmaf(sq[kk], w[kk], acc);
    g_c[b * H_ + h] = acc + bq[h] + bk[h];
}

// ---------- 2. fused GEMM + tanh + Wo reduction -> logits ----------
// Block tile: 64 rows (fixed b, 64 consecutive s) x 256 H cols. K-tiles of 32.
// Thread (tx=tid>>4, ty=tid&15): rows ty*4..+3, cols tx*16..+15 as 8 f32x2 pairs.
// Within a warp tx varies slowly -> B-tile smem reads are broadcast (conflict-free).
#define MT 64
#define KT 32
#define APAD 68  // 64 + 4: keeps float4 alignment (68*4 % 16 == 0), <=2-way conflicts

__global__ void __launch_bounds__(256) logit_kernel(const float* __restrict__ kten,
                                                    const float* __restrict__ Wo) {
    __shared__ float sA[KT][APAD];   // [kk][row]
    __shared__ float sB[KT][H_];     // [kk][h]
    __shared__ float sWo[H_];
    __shared__ float sC[H_];
    __shared__ float red[MT][17];

    const int b  = blockIdx.y;
    const int s0 = blockIdx.x * MT;
    const int tid = threadIdx.x;
    const int tx = tid >> 4;   // 0..15 column group (slow within warp)
    const int ty = tid & 15;   // 0..15 row group

    sWo[tid] = Wo[tid];
    sC[tid]  = g_c[b * H_ + tid];

    unsigned long long acc[4][8];
#pragma unroll
    for (int r = 0; r < 4; r++)
#pragma unroll
        for (int j = 0; j < 8; j++) acc[r][j] = 0ull;

    for (int k0 = 0; k0 < K_; k0 += KT) {
        // load A tile: 64 rows x 32 k (rows are k[(s)*B+b][k0..k0+31])
#pragma unroll
        for (int it = 0; it < 2; it++) {
            int f4  = tid + it * 256;        // 0..511 float4s
            int row = f4 >> 3;               // 8 float4 per row
            int c4  = (f4 & 7) * 4;
            float4 a4 = *(const float4*)(kten + ((s0 + row) * B_ + b) * K_ + k0 + c4);
            sA[c4 + 0][row] = a4.x;
            sA[c4 + 1][row] = a4.y;
            sA[c4 + 2][row] = a4.z;
            sA[c4 + 3][row] = a4.w;
        }
        // load B tile: 32 k x 256 h from k-major WkT (fully coalesced)
#pragma unroll
        for (int it = 0; it < 8; it++) {
            int f4 = tid + it * 256;         // 0..2047 float4s
            int kk = f4 >> 6;
            int h4 = (f4 & 63) * 4;
            *(float4*)&sB[kk][h4] = *(const float4*)(g_WkT + (k0 + kk) * H_ + h4);
        }
        __syncthreads();

#pragma unroll 8
        for (int kk = 0; kk < KT; kk++) {
            float4 av = *(const float4*)&sA[kk][ty * 4];
            unsigned long long a0 = pack2(av.x, av.x);
            unsigned long long a1 = pack2(av.y, av.y);
            unsigned long long a2 = pack2(av.z, av.z);
            unsigned long long a3 = pack2(av.w, av.w);
            const ulonglong2* bp = (const ulonglong2*)&sB[kk][tx * 16];
            ulonglong2 u0 = bp[0], u1 = bp[1], u2 = bp[2], u3 = bp[3];
            unsigned long long bv[8] = {u0.x, u0.y, u1.x, u1.y, u2.x, u2.y, u3.x, u3.y};
#pragma unroll
            for (int j = 0; j < 8; j++) {
                acc[0][j] = fma2(a0, bv[j], acc[0][j]);
                acc[1][j] = fma2(a1, bv[j], acc[1][j]);
                acc[2][j] = fma2(a2, bv[j], acc[2][j]);
                acc[3][j] = fma2(a3, bv[j], acc[3][j]);
            }
        }
        __syncthreads();
    }

    // epilogue: tanh(h_k + c) dot Wo, reduce across 16 col-groups
    float part[4];
#pragma unroll
    for (int r = 0; r < 4; r++) {
        float p = 0.f;
#pragma unroll
        for (int j = 0; j < 8; j++) {
            float2 hv = unpack2(acc[r][j]);
            int h0 = tx * 16 + 2 * j;
            p = fmaf(tanhf(hv.x + sC[h0]),     sWo[h0],     p);
            p = fmaf(tanhf(hv.y + sC[h0 + 1]), sWo[h0 + 1], p);
        }
        part[r] = p;
    }
#pragma unroll
    for (int r = 0; r < 4; r++) red[ty * 4 + r][tx] = part[r];
    __syncthreads();
    if (tid < MT) {
        float s = 0.f;
#pragma unroll
        for (int t = 0; t < 16; t++) s += red[tid][t];
        g_logit[b * S_ + s0 + tid] = s;  // bo omitted: softmax shift-invariant
    }
}

// ---------- 3. softmax over S per batch -> p into d_out ----------
__global__ void softmax_kernel(float* __restrict__ p_out) {
    __shared__ float sred[8];
    __shared__ float sbcast;
    const int b = blockIdx.x, tid = threadIdx.x;

    float mx = -1e30f;
    for (int s = tid; s < S_; s += 256) mx = fmaxf(mx, g_logit[b * S_ + s]);
#pragma unroll
    for (int o = 16; o; o >>= 1) mx = fmaxf(mx, __shfl_xor_sync(0xffffffffu, mx, o));
    if ((tid & 31) == 0) sred[tid >> 5] = mx;
    __syncthreads();
    if (tid < 32) {
        float v = (tid < 8) ? sred[tid] : -1e30f;
#pragma unroll
        for (int o = 4; o; o >>= 1) v = fmaxf(v, __shfl_xor_sync(0xffffffffu, v, o));
        if (tid == 0) sbcast = v;
    }
    __syncthreads();
    mx = sbcast;
    __syncthreads();

    float sum = 0.f;
    for (int s = tid; s < S_; s += 256) {
        float e = expf(g_logit[b * S_ + s] - mx);
        g_logit[b * S_ + s] = e;
        sum += e;
    }
#pragma unroll
    for (int o = 16; o; o >>= 1) sum += __shfl_xor_sync(0xffffffffu, sum, o);
    if ((tid & 31) == 0) sred[tid >> 5] = sum;
    __syncthreads();
    if (tid < 32) {
        float v = (tid < 8) ? sred[tid] : 0.f;
#pragma unroll
        for (int o = 4; o; o >>= 1) v += __shfl_xor_sync(0xffffffffu, v, o);
        if (tid == 0) sbcast = v;
    }
    __syncthreads();
    float inv = 1.f / sbcast;
    for (int s = tid; s < S_; s += 256) p_out[b * S_ + s] = g_logit[b * S_ + s] * inv;
}

// ---------- 4. out[b,v] = sum_s p[b,s] * v[s,b,v]  (split over s, 2-stage) ----------
__global__ void wsum_kernel(const float* __restrict__ v, const float* __restrict__ p) {
    const int b = blockIdx.y, sp = blockIdx.x, tid = threadIdx.x;
    const int col = tid * 2;
    const int SCH = S_ / NSPLIT;  // 128
    const int s0 = sp * SCH;
    const float* pb = p + b * S_;
    float2 acc = make_float2(0.f, 0.f);
#pragma unroll 4
    for (int i = 0; i < SCH; i++) {
        int s = s0 + i;
        float pv = __ldg(pb + s);
        float2 vv = *(const float2*)(v + ((size_t)s * B_ + b) * V_ + col);
        acc.x = fmaf(pv, vv.x, acc.x);
        acc.y = fmaf(pv, vv.y, acc.y);
    }
    float* dst = g_part + (b * NSPLIT + sp) * V_ + col;
    dst[0] = acc.x;
    dst[1] = acc.y;
}

__global__ void reduce_out(float* __restrict__ out) {
    const int b = blockIdx.x, tid = threadIdx.x;  // 512 threads
    float s = 0.f;
#pragma unroll
    for (int i = 0; i < NSPLIT; i++) s += g_part[(b * NSPLIT + i) * V_ + tid];
    out[b * V_ + tid] = s;
}

// ---------- launch ----------
extern "C" void kernel_launch(void* const* d_in, const int* in_sizes, int n_in,
                              void* d_out, int out_size) {
    const float* q  = (const float*)d_in[0];
    const float* k  = (const float*)d_in[1];
    const float* v  = (const float*)d_in[2];
    const float* Wk = (const float*)d_in[3];
    const float* bk = (const float*)d_in[4];
    const float* Wq = (const float*)d_in[5];
    const float* bq = (const float*)d_in[6];
    const float* Wo = (const float*)d_in[7];
    // d_in[8] = bo: provably irrelevant (softmax shift invariance)

    float* out = (float*)d_out;      // [0, B*V): out[1,B,V]
    float* p   = out + B_ * V_;      // [B*V, B*V+B*S): p[B,S]

    transpose_wk<<<(K_ * H_ + 511) / 512, 512>>>(Wk);
    hq_kernel<<<B_, H_>>>(q, Wq, bq, bk);
    logit_kernel<<<dim3(S_ / MT, B_), 256>>>(k, Wo);
    softmax_kernel<<<B_, 256>>>(p);
    wsum_kernel<<<dim3(NSPLIT, B_), 256>>>(v, p);
    reduce_out<<<B_, V_>>>(out);
}

// round 9
// speedup vs baseline: 1.4983x; 1.4983x over previous
#include <cuda_runtime.h>
#include <cuda_bf16.h>
#include <cstdint>

#define B_ 32
#define S_ 2048
#define K_ 512
#define V_ 512
#define H_ 256
#define NSPLIT 16

// ---------------- device scratch (allocation-free contract) ----------------
__device__ float g_c[B_ * H_];               // bk + bq + q@Wq.T per (b,h)
__device__ float g_logit[B_ * S_];
__device__ float g_part[B_ * NSPLIT * V_];
__device__ __align__(16) __nv_bfloat16 g_Wkh[H_ * K_];  // Wk hi bf16, [H][K] k-major
__device__ __align__(16) __nv_bfloat16 g_Wkl[H_ * K_];  // Wk residual bf16

// ---------------- helpers ----------------
static __device__ __forceinline__ uint32_t smem_u32(const void* p) {
    uint32_t a;
    asm("{ .reg .u64 t; cvta.to.shared.u64 t, %1; cvt.u32.u64 %0, t; }" : "=r"(a) : "l"(p));
    return a;
}
static __device__ __forceinline__ uint32_t pack_bf(float x, float y) {
    uint16_t ux = __bfloat16_as_ushort(__float2bfloat16(x));
    uint16_t uy = __bfloat16_as_ushort(__float2bfloat16(y));
    return (uint32_t)ux | ((uint32_t)uy << 16);
}
static __device__ __forceinline__ void ldm_x4(uint32_t* r, uint32_t addr) {
    asm volatile("ldmatrix.sync.aligned.m8n8.x4.shared.b16 {%0,%1,%2,%3}, [%4];"
                 : "=r"(r[0]), "=r"(r[1]), "=r"(r[2]), "=r"(r[3]) : "r"(addr));
}
static __device__ __forceinline__ void mma16816(float* d, const uint32_t* a,
                                                uint32_t b0, uint32_t b1) {
    asm volatile(
        "mma.sync.aligned.m16n8k16.row.col.f32.bf16.bf16.f32 "
        "{%0,%1,%2,%3}, {%4,%5,%6,%7}, {%8,%9}, {%0,%1,%2,%3};"
        : "+f"(d[0]), "+f"(d[1]), "+f"(d[2]), "+f"(d[3])
        : "r"(a[0]), "r"(a[1]), "r"(a[2]), "r"(a[3]), "r"(b0), "r"(b1));
}
#define CP16(dst, src) \
    asm volatile("cp.async.cg.shared.global [%0], [%1], 16;" :: "r"(dst), "l"(src) : "memory")
#define CPCOMMIT() asm volatile("cp.async.commit_group;" ::: "memory")
#define CPWAIT0()  asm volatile("cp.async.wait_group 0;" ::: "memory")

// ---------------- 0. split Wk fp32 -> (hi, lo) bf16, K-major as-is ----------------
__global__ void prep_wk(const float* __restrict__ Wk) {
    int idx = blockIdx.x * 256 + threadIdx.x;
    if (idx < H_ * K_) {
        float w = Wk[idx];
        __nv_bfloat16 h = __float2bfloat16(w);
        g_Wkh[idx] = h;
        g_Wkl[idx] = __float2bfloat16(w - __bfloat162float(h));
    }
}

// ---------------- 1. c[b,h] = bk[h] + bq[h] + q[b]·Wq[h] ----------------
__global__ void hq_kernel(const float* __restrict__ q, const float* __restrict__ Wq,
                          const float* __restrict__ bq, const float* __restrict__ bk) {
    __shared__ float sq[K_];
    int b = blockIdx.x, h = threadIdx.x;
    for (int i = h; i < K_; i += H_) sq[i] = q[b * K_ + i];
    __syncthreads();
    const float* w = Wq + h * K_;
    float acc = 0.f;
#pragma unroll 8
    for (int kk = 0; kk < K_; kk++) acc = fmaf(sq[kk], w[kk], acc);
    g_c[b * H_ + h] = acc + bq[h] + bk[h];
}

// ---------------- 2. HMMA GEMM (3x bf16 split) + fused tanh/Wo epilogue ----------
// CTA: M=128 (one b, 128 s) x N=256 (all H). K chunks of 32, double-buffered.
// 8 warps as 2(M) x 4(N); warp tile 64x64; acc fp32 in registers.
#define MT 128
#define BK 32
#define NC (K_ / BK)       // 16 chunks
#define THREADS 256
#define ROWB 80            // padded row: 32 bf16 = 64 B data + 16 B pad

#define OFF_C   0
#define OFF_WO  1024
#define OFF_RED 2048
#define OFF_T   4096
#define T_AH 0
#define T_AL 10240
#define T_BH 20480
#define T_BL 40960
#define STAGE 61440
#define SMEM_TOTAL (OFF_T + 2 * STAGE)   // 126976 B

__global__ void __launch_bounds__(THREADS, 1) logit_kernel(const float* __restrict__ kten,
                                                           const float* __restrict__ Wo) {
    extern __shared__ char smem[];
    const uint32_t sbase = smem_u32(smem);
    const int tid  = threadIdx.x;
    const int wid  = tid >> 5;
    const int lane = tid & 31;
    const int mw = wid >> 2;      // 0..1
    const int nw = wid & 3;       // 0..3
    const int b  = blockIdx.y;
    const int s0 = blockIdx.x * MT;

    {
        float* sC = (float*)(smem + OFF_C);
        float* sW = (float*)(smem + OFF_WO);
        sC[tid] = g_c[b * H_ + tid];
        sW[tid] = Wo[tid];
    }

    const float* abase = kten + ((size_t)s0 * B_ + b) * K_;  // row stride B_*K_

    // ldmatrix lane addressing (bytes). Non-trans for BOTH A and B:
    // lanes 0-15 -> rows 0-15 at k-bytes 0; lanes 16-31 -> rows 0-15 at k-bytes 16.
    // regs: r0 = rows0-7/k0-7, r1 = rows8-15/k0-7, r2 = rows0-7/k8-15, r3 = rows8-15/k8-15
    const uint32_t fragLane = (uint32_t)(lane & 15) * ROWB + (uint32_t)(lane >> 4) * 16u;
    const uint32_t aWarp = (uint32_t)mw * 64u * ROWB;
    const uint32_t bWarp = (uint32_t)nw * 64u * ROWB;

    float acc[4][8][4];
#pragma unroll
    for (int mt = 0; mt < 4; ++mt)
#pragma unroll
        for (int nt = 0; nt < 8; ++nt)
#pragma unroll
            for (int r = 0; r < 4; ++r) acc[mt][nt][r] = 0.f;

    float4 areg[4];

    // ---- loaders (macros over locals) ----
#define LDG_A(c)                                                                     \
    {                                                                                \
        const int k0 = (c) * BK;                                                     \
        _Pragma("unroll")                                                            \
        for (int i = 0; i < 4; ++i) {                                                \
            int idx = tid + i * 256;                                                 \
            int row = idx >> 3, c4 = idx & 7;                                        \
            areg[i] = *(const float4*)(abase + (size_t)row * (B_ * K_) + k0 + c4 * 4); \
        }                                                                            \
    }
#define STS_A(stg)                                                                   \
    {                                                                                \
        char* sb = smem + OFF_T + (stg) * STAGE;                                     \
        _Pragma("unroll")                                                            \
        for (int i = 0; i < 4; ++i) {                                                \
            int idx = tid + i * 256;                                                 \
            int row = idx >> 3, c4 = idx & 7;                                        \
            float4 v = areg[i];                                                      \
            uint32_t h01 = pack_bf(v.x, v.y), h23 = pack_bf(v.z, v.w);               \
            float r0 = v.x - __bfloat162float(__ushort_as_bfloat16((uint16_t)h01));  \
            float r1 = v.y - __bfloat162float(__ushort_as_bfloat16((uint16_t)(h01 >> 16))); \
            float r2 = v.z - __bfloat162float(__ushort_as_bfloat16((uint16_t)h23));  \
            float r3 = v.w - __bfloat162float(__ushort_as_bfloat16((uint16_t)(h23 >> 16))); \
            uint32_t off = (uint32_t)row * ROWB + (uint32_t)c4 * 8u;                 \
            *(uint2*)(sb + T_AH + off) = make_uint2(h01, h23);                       \
            *(uint2*)(sb + T_AL + off) = make_uint2(pack_bf(r0, r1), pack_bf(r2, r3)); \
        }                                                                            \
    }
#define CPA_B(c, stg)                                                                \
    {                                                                                \
        const int k0 = (c) * BK;                                                     \
        uint32_t sb = sbase + OFF_T + (stg) * STAGE;                                 \
        _Pragma("unroll")                                                            \
        for (int i = 0; i < 4; ++i) {                                                \
            int idx = tid + i * 256;                                                 \
            int row = idx >> 2, c8 = idx & 3;                                        \
            uint32_t off = (uint32_t)row * ROWB + (uint32_t)c8 * 16u;                \
            CP16(sb + T_BH + off, (const char*)(g_Wkh + row * K_ + k0 + c8 * 8));    \
            CP16(sb + T_BL + off, (const char*)(g_Wkl + row * K_ + k0 + c8 * 8));    \
        }                                                                            \
        CPCOMMIT();                                                                  \
    }

    // prologue: chunk 0 into stage 0
    LDG_A(0);
    CPA_B(0, 0);
    STS_A(0);
    CPWAIT0();
    __syncthreads();

    for (int c = 0; c < NC; ++c) {
        const int st = c & 1;
        if (c + 1 < NC) {
            LDG_A(c + 1);
            CPA_B(c + 1, st ^ 1);
        }
        // ---- compute chunk c from stage st ----
        {
            const uint32_t sb = sbase + OFF_T + (uint32_t)st * STAGE;
#pragma unroll
            for (int ks = 0; ks < 2; ++ks) {
                uint32_t ah[4][4], al[4][4];
                const uint32_t aoff = sb + T_AH + aWarp + fragLane + (uint32_t)ks * 32u;
#pragma unroll
                for (int mt = 0; mt < 4; ++mt) {
                    ldm_x4(ah[mt], aoff + (uint32_t)mt * (16u * ROWB));
                    ldm_x4(al[mt], aoff + (uint32_t)mt * (16u * ROWB) + (T_AL - T_AH));
                }
                const uint32_t boff = sb + T_BH + bWarp + fragLane + (uint32_t)ks * 32u;
#pragma unroll
                for (int ntp = 0; ntp < 4; ++ntp) {
                    uint32_t bh[4], bl[4];
                    ldm_x4(bh, boff + (uint32_t)ntp * (16u * ROWB));
                    ldm_x4(bl, boff + (uint32_t)ntp * (16u * ROWB) + (T_BL - T_BH));
#pragma unroll
                    for (int mt = 0; mt < 4; ++mt) {
                        float* d0 = acc[mt][ntp * 2];       // n-cols ntp*16 + 0..7
                        float* d1 = acc[mt][ntp * 2 + 1];   // n-cols ntp*16 + 8..15
                        mma16816(d0, ah[mt], bh[0], bh[2]);
                        mma16816(d0, al[mt], bh[0], bh[2]);
                        mma16816(d0, ah[mt], bl[0], bl[2]);
                        mma16816(d1, ah[mt], bh[1], bh[3]);
                        mma16816(d1, al[mt], bh[1], bh[3]);
                        mma16816(d1, ah[mt], bl[1], bl[3]);
                    }
                }
            }
        }
        if (c + 1 < NC) {
            STS_A((c + 1) & 1);   // FIX: stage index, not chunk index
            CPWAIT0();
            __syncthreads();
        }
    }

    // ---- epilogue: tanh(h + c) dot Wo, reduce ----
    {
        const float* sC = (const float*)(smem + OFF_C);
        const float* sW = (const float*)(smem + OFF_WO);
        float* red = (float*)(smem + OFF_RED);
        __syncthreads();
#pragma unroll
        for (int mt = 0; mt < 4; ++mt) {
            float sl = 0.f, sh = 0.f;
#pragma unroll
            for (int nt = 0; nt < 8; ++nt) {
                int h0 = nw * 64 + nt * 8 + (lane & 3) * 2;
                float c0 = sC[h0], c1 = sC[h0 + 1];
                float w0 = sW[h0], w1 = sW[h0 + 1];
                // fast tanh: sign(x) * (1 - 2/(exp(2|x|)+1))
#define FTANH(x) ({ float _x = (x); float _a = fabsf(_x);                        \
                    float _t = 1.f - __fdividef(2.f, __expf(_a + _a) + 1.f);     \
                    copysignf(_t, _x); })
                sl = fmaf(FTANH(acc[mt][nt][0] + c0), w0, sl);
                sl = fmaf(FTANH(acc[mt][nt][1] + c1), w1, sl);
                sh = fmaf(FTANH(acc[mt][nt][2] + c0), w0, sh);
                sh = fmaf(FTANH(acc[mt][nt][3] + c1), w1, sh);
#undef FTANH
            }
            sl += __shfl_xor_sync(0xffffffffu, sl, 1);
            sl += __shfl_xor_sync(0xffffffffu, sl, 2);
            sh += __shfl_xor_sync(0xffffffffu, sh, 1);
            sh += __shfl_xor_sync(0xffffffffu, sh, 2);
            if ((lane & 3) == 0) {
                int r = mw * 64 + mt * 16 + (lane >> 2);
                red[r * 4 + nw]       = sl;
                red[(r + 8) * 4 + nw] = sh;
            }
        }
        __syncthreads();
        if (tid < MT) {
            float s = red[tid * 4] + red[tid * 4 + 1] + red[tid * 4 + 2] + red[tid * 4 + 3];
            g_logit[b * S_ + s0 + tid] = s;  // bo omitted: softmax shift-invariant
        }
    }
}

// ---------------- 3. softmax over S per batch -> p ----------------
__global__ void softmax_kernel(float* __restrict__ p_out) {
    __shared__ float sred[8];
    __shared__ float sbcast;
    const int b = blockIdx.x, tid = threadIdx.x;

    float mx = -1e30f;
    for (int s = tid; s < S_; s += 256) mx = fmaxf(mx, g_logit[b * S_ + s]);
#pragma unroll
    for (int o = 16; o; o >>= 1) mx = fmaxf(mx, __shfl_xor_sync(0xffffffffu, mx, o));
    if ((tid & 31) == 0) sred[tid >> 5] = mx;
    __syncthreads();
    if (tid < 32) {
        float v = (tid < 8) ? sred[tid] : -1e30f;
#pragma unroll
        for (int o = 4; o; o >>= 1) v = fmaxf(v, __shfl_xor_sync(0xffffffffu, v, o));
        if (tid == 0) sbcast = v;
    }
    __syncthreads();
    mx = sbcast;
    __syncthreads();

    float sum = 0.f;
    for (int s = tid; s < S_; s += 256) {
        float e = expf(g_logit[b * S_ + s] - mx);
        g_logit[b * S_ + s] = e;
        sum += e;
    }
#pragma unroll
    for (int o = 16; o; o >>= 1) sum += __shfl_xor_sync(0xffffffffu, sum, o);
    if ((tid & 31) == 0) sred[tid >> 5] = sum;
    __syncthreads();
    if (tid < 32) {
        float v = (tid < 8) ? sred[tid] : 0.f;
#pragma unroll
        for (int o = 4; o; o >>= 1) v += __shfl_xor_sync(0xffffffffu, v, o);
        if (tid == 0) sbcast = v;
    }
    __syncthreads();
    float inv = 1.f / sbcast;
    for (int s = tid; s < S_; s += 256) p_out[b * S_ + s] = g_logit[b * S_ + s] * inv;
}

// ---------------- 4. out[b,:] = sum_s p[b,s] * v[s,b,:] ----------------
__global__ void wsum_kernel(const float* __restrict__ v, const float* __restrict__ p) {
    const int b = blockIdx.y, sp = blockIdx.x, tid = threadIdx.x;
    const int col = tid * 2;
    const int SCH = S_ / NSPLIT;
    const int s0 = sp * SCH;
    const float* pb = p + b * S_;
    float2 acc = make_float2(0.f, 0.f);
#pragma unroll 4
    for (int i = 0; i < SCH; i++) {
        int s = s0 + i;
        float pv = __ldg(pb + s);
        float2 vv = *(const float2*)(v + ((size_t)s * B_ + b) * V_ + col);
        acc.x = fmaf(pv, vv.x, acc.x);
        acc.y = fmaf(pv, vv.y, acc.y);
    }
    float* dst = g_part + (b * NSPLIT + sp) * V_ + col;
    dst[0] = acc.x;
    dst[1] = acc.y;
}

__global__ void reduce_out(float* __restrict__ out) {
    const int b = blockIdx.x, tid = threadIdx.x;
    float s = 0.f;
#pragma unroll
    for (int i = 0; i < NSPLIT; i++) s += g_part[(b * NSPLIT + i) * V_ + tid];
    out[b * V_ + tid] = s;
}

// ---------------- launch ----------------
extern "C" void kernel_launch(void* const* d_in, const int* in_sizes, int n_in,
                              void* d_out, int out_size) {
    const float* q  = (const float*)d_in[0];
    const float* k  = (const float*)d_in[1];
    const float* v  = (const float*)d_in[2];
    const float* Wk = (const float*)d_in[3];
    const float* bk = (const float*)d_in[4];
    const float* Wq = (const float*)d_in[5];
    const float* bq = (const float*)d_in[6];
    const float* Wo = (const float*)d_in[7];
    // d_in[8] = bo: irrelevant under softmax shift invariance

    float* out = (float*)d_out;    // out[1,B,V]
    float* p   = out + B_ * V_;    // p[B,S]

    cudaFuncSetAttribute(logit_kernel, cudaFuncAttributeMaxDynamicSharedMemorySize, SMEM_TOTAL);

    prep_wk<<<(H_ * K_ + 255) / 256, 256>>>(Wk);
    hq_kernel<<<B_, H_>>>(q, Wq, bq, bk);
    logit_kernel<<<dim3(S_ / MT, B_), THREADS, SMEM_TOTAL>>>(k, Wo);
    softmax_kernel<<<B_, 256>>>(p);
    wsum_kernel<<<dim3(NSPLIT, B_), 256>>>(v, p);
    reduce_out<<<B_, V_>>>(out);
}

// round 10
// speedup vs baseline: 1.5128x; 1.0097x over previous
#include <cuda_runtime.h>
#include <cuda_bf16.h>
#include <cstdint>

#define B_ 32
#define S_ 2048
#define K_ 512
#define V_ 512
#define H_ 256
#define NSPLIT 16

// ---------------- device scratch (allocation-free contract) ----------------
__device__ float g_c[B_ * H_];               // bk + bq + q@Wq.T per (b,h)
__device__ float g_logit[B_ * S_];
__device__ float g_part[B_ * NSPLIT * V_];
__device__ __align__(16) __nv_bfloat16 g_Wkh[H_ * K_];  // Wk hi bf16, [H][K] k-major
__device__ __align__(16) __nv_bfloat16 g_Wkl[H_ * K_];  // Wk residual bf16

// ---------------- helpers ----------------
static __device__ __forceinline__ uint32_t smem_u32(const void* p) {
    uint32_t a;
    asm("{ .reg .u64 t; cvta.to.shared.u64 t, %1; cvt.u32.u64 %0, t; }" : "=r"(a) : "l"(p));
    return a;
}
static __device__ __forceinline__ uint32_t pack_bf(float x, float y) {
    uint16_t ux = __bfloat16_as_ushort(__float2bfloat16(x));
    uint16_t uy = __bfloat16_as_ushort(__float2bfloat16(y));
    return (uint32_t)ux | ((uint32_t)uy << 16);
}
static __device__ __forceinline__ void ldm_x4(uint32_t* r, uint32_t addr) {
    asm volatile("ldmatrix.sync.aligned.m8n8.x4.shared.b16 {%0,%1,%2,%3}, [%4];"
                 : "=r"(r[0]), "=r"(r[1]), "=r"(r[2]), "=r"(r[3]) : "r"(addr));
}
static __device__ __forceinline__ void mma16816(float* d, const uint32_t* a,
                                                uint32_t b0, uint32_t b1) {
    asm volatile(
        "mma.sync.aligned.m16n8k16.row.col.f32.bf16.bf16.f32 "
        "{%0,%1,%2,%3}, {%4,%5,%6,%7}, {%8,%9}, {%0,%1,%2,%3};"
        : "+f"(d[0]), "+f"(d[1]), "+f"(d[2]), "+f"(d[3])
        : "r"(a[0]), "r"(a[1]), "r"(a[2]), "r"(a[3]), "r"(b0), "r"(b1));
}
#define CP16(dst, src) \
    asm volatile("cp.async.cg.shared.global [%0], [%1], 16;" :: "r"(dst), "l"(src) : "memory")
#define CPCOMMIT() asm volatile("cp.async.commit_group;" ::: "memory")
#define CPWAIT0()  asm volatile("cp.async.wait_group 0;" ::: "memory")

// ---------------- 0. split Wk fp32 -> (hi, lo) bf16, K-major as-is ----------------
__global__ void prep_wk(const float* __restrict__ Wk) {
    int idx = blockIdx.x * 256 + threadIdx.x;
    if (idx < H_ * K_) {
        float w = Wk[idx];
        __nv_bfloat16 h = __float2bfloat16(w);
        g_Wkh[idx] = h;
        g_Wkl[idx] = __float2bfloat16(w - __bfloat162float(h));
    }
}

// ---------------- 1. c[b,h] = bk[h] + bq[h] + q[b]·Wq[h] ----------------
__global__ void hq_kernel(const float* __restrict__ q, const float* __restrict__ Wq,
                          const float* __restrict__ bq, const float* __restrict__ bk) {
    __shared__ float sq[K_];
    int b = blockIdx.x, h = threadIdx.x;
    for (int i = h; i < K_; i += H_) sq[i] = q[b * K_ + i];
    __syncthreads();
    const float* w = Wq + h * K_;
    float acc = 0.f;
#pragma unroll 8
    for (int kk = 0; kk < K_; kk++) acc = fmaf(sq[kk], w[kk], acc);
    g_c[b * H_ + h] = acc + bq[h] + bk[h];
}

// ---------------- 2. HMMA GEMM (3x bf16 split) + fused tanh/Wo epilogue ----------
// CTA: M=128 (one b, 128 s) x N=256 (all H). K chunks of 32, double-buffered.
// 16 warps as 4(M) x 4(N); warp tile 32x64; acc fp32 in registers.
#define MT 128
#define BK 32
#define NC (K_ / BK)       // 16 chunks
#define THREADS 512
#define ROWB 80            // padded row: 32 bf16 = 64 B data + 16 B pad

#define OFF_C   0
#define OFF_WO  1024
#define OFF_RED 2048
#define OFF_T   4096
#define T_AH 0
#define T_AL 10240
#define T_BH 20480
#define T_BL 40960
#define STAGE 61440
#define SMEM_TOTAL (OFF_T + 2 * STAGE)   // 126976 B

__global__ void __launch_bounds__(THREADS, 1) logit_kernel(const float* __restrict__ kten,
                                                           const float* __restrict__ Wo) {
    extern __shared__ char smem[];
    const uint32_t sbase = smem_u32(smem);
    const int tid  = threadIdx.x;
    const int wid  = tid >> 5;
    const int lane = tid & 31;
    const int mw = wid >> 2;      // 0..3 (M groups of 32 rows)
    const int nw = wid & 3;       // 0..3 (N groups of 64 cols)
    const int b  = blockIdx.y;
    const int s0 = blockIdx.x * MT;

    if (tid < H_) {
        ((float*)(smem + OFF_C))[tid]  = g_c[b * H_ + tid];
        ((float*)(smem + OFF_WO))[tid] = Wo[tid];
    }

    const float* abase = kten + ((size_t)s0 * B_ + b) * K_;  // row stride B_*K_

    // ldmatrix lane addressing (bytes). Non-trans for BOTH A and B:
    // regs: r0 = rows0-7/k0-7, r1 = rows8-15/k0-7, r2 = rows0-7/k8-15, r3 = rows8-15/k8-15
    const uint32_t fragLane = (uint32_t)(lane & 15) * ROWB + (uint32_t)(lane >> 4) * 16u;
    const uint32_t aWarp = (uint32_t)mw * 32u * ROWB;
    const uint32_t bWarp = (uint32_t)nw * 64u * ROWB;

    float acc[2][8][4];
#pragma unroll
    for (int mt = 0; mt < 2; ++mt)
#pragma unroll
        for (int nt = 0; nt < 8; ++nt)
#pragma unroll
            for (int r = 0; r < 4; ++r) acc[mt][nt][r] = 0.f;

    float4 areg[2];

    // ---- loaders (macros over locals) ----
#define LDG_A(c)                                                                     \
    {                                                                                \
        const int k0 = (c) * BK;                                                     \
        _Pragma("unroll")                                                            \
        for (int i = 0; i < 2; ++i) {                                                \
            int idx = tid + i * 512;                                                 \
            int row = idx >> 3, c4 = idx & 7;                                        \
            areg[i] = *(const float4*)(abase + (size_t)row * (B_ * K_) + k0 + c4 * 4); \
        }                                                                            \
    }
#define STS_A(stg)                                                                   \
    {                                                                                \
        char* sb = smem + OFF_T + (stg) * STAGE;                                     \
        _Pragma("unroll")                                                            \
        for (int i = 0; i < 2; ++i) {                                                \
            int idx = tid + i * 512;                                                 \
            int row = idx >> 3, c4 = idx & 7;                                        \
            float4 v = areg[i];                                                      \
            uint32_t h01 = pack_bf(v.x, v.y), h23 = pack_bf(v.z, v.w);               \
            float r0 = v.x - __bfloat162float(__ushort_as_bfloat16((uint16_t)h01));  \
            float r1 = v.y - __bfloat162float(__ushort_as_bfloat16((uint16_t)(h01 >> 16))); \
            float r2 = v.z - __bfloat162float(__ushort_as_bfloat16((uint16_t)h23));  \
            float r3 = v.w - __bfloat162float(__ushort_as_bfloat16((uint16_t)(h23 >> 16))); \
            uint32_t off = (uint32_t)row * ROWB + (uint32_t)c4 * 8u;                 \
            *(uint2*)(sb + T_AH + off) = make_uint2(h01, h23);                       \
            *(uint2*)(sb + T_AL + off) = make_uint2(pack_bf(r0, r1), pack_bf(r2, r3)); \
        }                                                                            \
    }
#define CPA_B(c, stg)                                                                \
    {                                                                                \
        const int k0 = (c) * BK;                                                     \
        uint32_t sb = sbase + OFF_T + (stg) * STAGE;                                 \
        _Pragma("unroll")                                                            \
        for (int i = 0; i < 2; ++i) {                                                \
            int idx = tid + i * 512;                                                 \
            int row = idx >> 2, c8 = idx & 3;                                        \
            uint32_t off = (uint32_t)row * ROWB + (uint32_t)c8 * 16u;                \
            CP16(sb + T_BH + off, (const char*)(g_Wkh + row * K_ + k0 + c8 * 8));    \
            CP16(sb + T_BL + off, (const char*)(g_Wkl + row * K_ + k0 + c8 * 8));    \
        }                                                                            \
        CPCOMMIT();                                                                  \
    }

    // prologue: chunk 0 into stage 0
    LDG_A(0);
    CPA_B(0, 0);
    STS_A(0);
    CPWAIT0();
    __syncthreads();

#pragma unroll 1
    for (int c = 0; c < NC; ++c) {
        const int st = c & 1;
        if (c + 1 < NC) {
            LDG_A(c + 1);
            CPA_B(c + 1, st ^ 1);
        }
        // ---- compute chunk c from stage st ----
        {
            const uint32_t sb = sbase + OFF_T + (uint32_t)st * STAGE;
#pragma unroll
            for (int ks = 0; ks < 2; ++ks) {
                uint32_t ah[2][4], al[2][4];
                const uint32_t aoff = sb + T_AH + aWarp + fragLane + (uint32_t)ks * 32u;
#pragma unroll
                for (int mt = 0; mt < 2; ++mt) {
                    ldm_x4(ah[mt], aoff + (uint32_t)mt * (16u * ROWB));
                    ldm_x4(al[mt], aoff + (uint32_t)mt * (16u * ROWB) + (T_AL - T_AH));
                }
                const uint32_t boff = sb + T_BH + bWarp + fragLane + (uint32_t)ks * 32u;
#pragma unroll
                for (int ntp = 0; ntp < 4; ++ntp) {
                    uint32_t bh[4], bl[4];
                    ldm_x4(bh, boff + (uint32_t)ntp * (16u * ROWB));
                    ldm_x4(bl, boff + (uint32_t)ntp * (16u * ROWB) + (T_BL - T_BH));
                    float* D00 = acc[0][ntp * 2];       // mt0, n 0..7
                    float* D10 = acc[1][ntp * 2];       // mt1, n 0..7
                    float* D01 = acc[0][ntp * 2 + 1];   // mt0, n 8..15
                    float* D11 = acc[1][ntp * 2 + 1];   // mt1, n 8..15
                    // round-robin across 4 accumulators: RAW distance 4
                    mma16816(D00, ah[0], bh[0], bh[2]);
                    mma16816(D10, ah[1], bh[0], bh[2]);
                    mma16816(D01, ah[0], bh[1], bh[3]);
                    mma16816(D11, ah[1], bh[1], bh[3]);
                    mma16816(D00, al[0], bh[0], bh[2]);
                    mma16816(D10, al[1], bh[0], bh[2]);
                    mma16816(D01, al[0], bh[1], bh[3]);
                    mma16816(D11, al[1], bh[1], bh[3]);
                    mma16816(D00, ah[0], bl[0], bl[2]);
                    mma16816(D10, ah[1], bl[0], bl[2]);
                    mma16816(D01, ah[0], bl[1], bl[3]);
                    mma16816(D11, ah[1], bl[1], bl[3]);
                }
            }
        }
        if (c + 1 < NC) {
            STS_A((c + 1) & 1);
            CPWAIT0();
            __syncthreads();
        }
    }

    // ---- epilogue: tanh(h + c) dot Wo, reduce ----
    {
        const float* sC = (const float*)(smem + OFF_C);
        const float* sW = (const float*)(smem + OFF_WO);
        float* red = (float*)(smem + OFF_RED);
        __syncthreads();
#pragma unroll
        for (int mt = 0; mt < 2; ++mt) {
            float sl = 0.f, sh = 0.f;
#pragma unroll
            for (int nt = 0; nt < 8; ++nt) {
                int h0 = nw * 64 + nt * 8 + (lane & 3) * 2;
                float c0 = sC[h0], c1 = sC[h0 + 1];
                float w0 = sW[h0], w1 = sW[h0 + 1];
                // fast tanh: sign(x) * (1 - 2/(exp(2|x|)+1))
#define FTANH(x) ({ float _x = (x); float _a = fabsf(_x);                        \
                    float _t = 1.f - __fdividef(2.f, __expf(_a + _a) + 1.f);     \
                    copysignf(_t, _x); })
                sl = fmaf(FTANH(acc[mt][nt][0] + c0), w0, sl);
                sl = fmaf(FTANH(acc[mt][nt][1] + c1), w1, sl);
                sh = fmaf(FTANH(acc[mt][nt][2] + c0), w0, sh);
                sh = fmaf(FTANH(acc[mt][nt][3] + c1), w1, sh);
#undef FTANH
            }
            sl += __shfl_xor_sync(0xffffffffu, sl, 1);
            sl += __shfl_xor_sync(0xffffffffu, sl, 2);
            sh += __shfl_xor_sync(0xffffffffu, sh, 1);
            sh += __shfl_xor_sync(0xffffffffu, sh, 2);
            if ((lane & 3) == 0) {
                int r = mw * 32 + mt * 16 + (lane >> 2);
                red[r * 4 + nw]       = sl;
                red[(r + 8) * 4 + nw] = sh;
            }
        }
        __syncthreads();
        if (tid < MT) {
            float s = red[tid * 4] + red[tid * 4 + 1] + red[tid * 4 + 2] + red[tid * 4 + 3];
            g_logit[b * S_ + s0 + tid] = s;  // bo omitted: softmax shift-invariant
        }
    }
}

// ---------------- 3. softmax over S per batch -> p ----------------
__global__ void softmax_kernel(float* __restrict__ p_out) {
    __shared__ float sred[8];
    __shared__ float sbcast;
    const int b = blockIdx.x, tid = threadIdx.x;

    float mx = -1e30f;
    for (int s = tid; s < S_; s += 256) mx = fmaxf(mx, g_logit[b * S_ + s]);
#pragma unroll
    for (int o = 16; o; o >>= 1) mx = fmaxf(mx, __shfl_xor_sync(0xffffffffu, mx, o));
    if ((tid & 31) == 0) sred[tid >> 5] = mx;
    __syncthreads();
    if (tid < 32) {
        float v = (tid < 8) ? sred[tid] : -1e30f;
#pragma unroll
        for (int o = 4; o; o >>= 1) v = fmaxf(v, __shfl_xor_sync(0xffffffffu, v, o));
        if (tid == 0) sbcast = v;
    }
    __syncthreads();
    mx = sbcast;
    __syncthreads();

    float sum = 0.f;
    for (int s = tid; s < S_; s += 256) {
        float e = expf(g_logit[b * S_ + s] - mx);
        g_logit[b * S_ + s] = e;
        sum += e;
    }
#pragma unroll
    for (int o = 16; o; o >>= 1) sum += __shfl_xor_sync(0xffffffffu, sum, o);
    if ((tid & 31) == 0) sred[tid >> 5] = sum;
    __syncthreads();
    if (tid < 32) {
        float v = (tid < 8) ? sred[tid] : 0.f;
#pragma unroll
        for (int o = 4; o; o >>= 1) v += __shfl_xor_sync(0xffffffffu, v, o);
        if (tid == 0) sbcast = v;
    }
    __syncthreads();
    float inv = 1.f / sbcast;
    for (int s = tid; s < S_; s += 256) p_out[b * S_ + s] = g_logit[b * S_ + s] * inv;
}

// ---------------- 4. out[b,:] = sum_s p[b,s] * v[s,b,:] ----------------
__global__ void wsum_kernel(const float* __restrict__ v, const float* __restrict__ p) {
    const int b = blockIdx.y, sp = blockIdx.x, tid = threadIdx.x;
    const int col = tid * 2;
    const int SCH = S_ / NSPLIT;
    const int s0 = sp * SCH;
    const float* pb = p + b * S_;
    float2 acc = make_float2(0.f, 0.f);
#pragma unroll 4
    for (int i = 0; i < SCH; i++) {
        int s = s0 + i;
        float pv = __ldg(pb + s);
        float2 vv = *(const float2*)(v + ((size_t)s * B_ + b) * V_ + col);
        acc.x = fmaf(pv, vv.x, acc.x);
        acc.y = fmaf(pv, vv.y, acc.y);
    }
    float* dst = g_part + (b * NSPLIT + sp) * V_ + col;
    dst[0] = acc.x;
    dst[1] = acc.y;
}

__global__ void reduce_out(float* __restrict__ out) {
    const int b = blockIdx.x, tid = threadIdx.x;
    float s = 0.f;
#pragma unroll
    for (int i = 0; i < NSPLIT; i++) s += g_part[(b * NSPLIT + i) * V_ + tid];
    out[b * V_ + tid] = s;
}

// ---------------- launch ----------------
extern "C" void kernel_launch(void* const* d_in, const int* in_sizes, int n_in,
                              void* d_out, int out_size) {
    const float* q  = (const float*)d_in[0];
    const float* k  = (const float*)d_in[1];
    const float* v  = (const float*)d_in[2];
    const float* Wk = (const float*)d_in[3];
    const float* bk = (const float*)d_in[4];
    const float* Wq = (const float*)d_in[5];
    const float* bq = (const float*)d_in[6];
    const float* Wo = (const float*)d_in[7];
    // d_in[8] = bo: irrelevant under softmax shift invariance

    float* out = (float*)d_out;    // out[1,B,V]
    float* p   = out + B_ * V_;    // p[B,S]

    cudaFuncSetAttribute(logit_kernel, cudaFuncAttributeMaxDynamicSharedMemorySize, SMEM_TOTAL);

    prep_wk<<<(H_ * K_ + 255) / 256, 256>>>(Wk);
    hq_kernel<<<B_, H_>>>(q, Wq, bq, bk);
    logit_kernel<<<dim3(S_ / MT, B_), THREADS, SMEM_TOTAL>>>(k, Wo);
    softmax_kernel<<<B_, 256>>>(p);
    wsum_kernel<<<dim3(NSPLIT, B_), 256>>>(v, p);
    reduce_out<<<B_, V_>>>(out);
}

// round 12
// speedup vs baseline: 2.3466x; 1.5511x over previous
#include <cuda_runtime.h>
#include <cuda_fp16.h>
#include <cstdint>

#define B_ 32
#define S_ 2048
#define K_ 512
#define V_ 512
#define H_ 256
#define NSPLIT 16

// ---------------- device scratch (allocation-free contract) ----------------
__device__ float g_c[B_ * H_];               // bk + bq + q@Wq.T per (b,h)
__device__ float g_logit[B_ * S_];
__device__ float g_part[B_ * NSPLIT * V_];
__device__ __align__(16) __half g_Wkh[H_ * K_];   // Wk fp16, [H][K] k-major

// ---------------- helpers ----------------
static __device__ __forceinline__ uint32_t smem_u32(const void* p) {
    uint32_t a;
    asm("{ .reg .u64 t; cvta.to.shared.u64 t, %1; cvt.u32.u64 %0, t; }" : "=r"(a) : "l"(p));
    return a;
}
static __device__ __forceinline__ uint32_t pack_h2(float x, float y) {
    __half2 h = __floats2half2_rn(x, y);
    return *reinterpret_cast<uint32_t*>(&h);
}
static __device__ __forceinline__ void ldm_x4(uint32_t* r, uint32_t addr) {
    asm volatile("ldmatrix.sync.aligned.m8n8.x4.shared.b16 {%0,%1,%2,%3}, [%4];"
                 : "=r"(r[0]), "=r"(r[1]), "=r"(r[2]), "=r"(r[3]) : "r"(addr));
}
static __device__ __forceinline__ void mma16816(float* d, const uint32_t* a,
                                                uint32_t b0, uint32_t b1) {
    asm volatile(
        "mma.sync.aligned.m16n8k16.row.col.f32.f16.f16.f32 "
        "{%0,%1,%2,%3}, {%4,%5,%6,%7}, {%8,%9}, {%0,%1,%2,%3};"
        : "+f"(d[0]), "+f"(d[1]), "+f"(d[2]), "+f"(d[3])
        : "r"(a[0]), "r"(a[1]), "r"(a[2]), "r"(a[3]), "r"(b0), "r"(b1));
}
#define CP16(dst, src) \
    asm volatile("cp.async.cg.shared.global [%0], [%1], 16;" :: "r"(dst), "l"(src) : "memory")
#define CPCOMMIT() asm volatile("cp.async.commit_group;" ::: "memory")
#define CPWAIT0()  asm volatile("cp.async.wait_group 0;" ::: "memory")

// ---------------- 0. convert Wk fp32 -> fp16, K-major as-is ----------------
__global__ void prep_wk(const float* __restrict__ Wk) {
    int idx = blockIdx.x * 256 + threadIdx.x;
    if (idx < H_ * K_) g_Wkh[idx] = __float2half_rn(Wk[idx]);
}

// ---------------- 1. c[b,h] = bk[h] + bq[h] + q[b]·Wq[h] ----------------
__global__ void hq_kernel(const float* __restrict__ q, const float* __restrict__ Wq,
                          const float* __restrict__ bq, const float* __restrict__ bk) {
    __shared__ float sq[K_];
    int b = blockIdx.x, h = threadIdx.x;
    for (int i = h; i < K_; i += H_) sq[i] = q[b * K_ + i];
    __syncthreads();
    const float* w = Wq + h * K_;
    float acc = 0.f;
#pragma unroll 8
    for (int kk = 0; kk < K_; kk++) acc = fmaf(sq[kk], w[kk], acc);
    g_c[b * H_ + h] = acc + bq[h] + bk[h];
}

// ---------------- 2. single-pass fp16 HMMA GEMM + fused tanh/Wo epilogue ----------
// CTA: M=128 (one b, 128 s) x N=256 (all H). K chunks of 32, double-buffered.
// 16 warps as 4(M) x 4(N); warp tile 32x64; acc fp32 in registers.
#define MT 128
#define BK 32
#define NC (K_ / BK)       // 16 chunks
#define THREADS 512
#define ROWB 80            // padded row: 32 fp16 = 64 B data + 16 B pad

#define OFF_C   0
#define OFF_WO  1024
#define OFF_RED 2048
#define OFF_T   4096
#define T_A  0
#define T_B  10240
#define STAGE 30720
#define SMEM_TOTAL (OFF_T + 2 * STAGE)   // 65536 B

__global__ void __launch_bounds__(THREADS, 1) logit_kernel(const float* __restrict__ kten,
                                                           const float* __restrict__ Wo) {
    extern __shared__ char smem[];
    const uint32_t sbase = smem_u32(smem);
    const int tid  = threadIdx.x;
    const int wid  = tid >> 5;
    const int lane = tid & 31;
    const int mw = wid >> 2;      // 0..3 (M groups of 32 rows)
    const int nw = wid & 3;       // 0..3 (N groups of 64 cols)
    const int b  = blockIdx.y;
    const int s0 = blockIdx.x * MT;

    if (tid < H_) {
        ((float*)(smem + OFF_C))[tid]  = g_c[b * H_ + tid];
        ((float*)(smem + OFF_WO))[tid] = Wo[tid];
    }

    const float* abase = kten + ((size_t)s0 * B_ + b) * K_;  // row stride B_*K_

    // ldmatrix lane addressing (bytes). Non-trans for BOTH A and B:
    // regs: r0 = rows0-7/k0-7, r1 = rows8-15/k0-7, r2 = rows0-7/k8-15, r3 = rows8-15/k8-15
    const uint32_t fragLane = (uint32_t)(lane & 15) * ROWB + (uint32_t)(lane >> 4) * 16u;
    const uint32_t aWarp = (uint32_t)mw * 32u * ROWB;
    const uint32_t bWarp = (uint32_t)nw * 64u * ROWB;

    float acc[2][8][4];
#pragma unroll
    for (int mt = 0; mt < 2; ++mt)
#pragma unroll
        for (int nt = 0; nt < 8; ++nt)
#pragma unroll
            for (int r = 0; r < 4; ++r) acc[mt][nt][r] = 0.f;

    float4 areg[2];

    // ---- loaders (macros over locals) ----
#define LDG_A(c)                                                                     \
    {                                                                                \
        const int k0 = (c) * BK;                                                     \
        _Pragma("unroll")                                                            \
        for (int i = 0; i < 2; ++i) {                                                \
            int idx = tid + i * 512;                                                 \
            int row = idx >> 3, c4 = idx & 7;                                        \
            areg[i] = *(const float4*)(abase + (size_t)row * (B_ * K_) + k0 + c4 * 4); \
        }                                                                            \
    }
#define STS_A(stg)                                                                   \
    {                                                                                \
        char* sb = smem + OFF_T + (stg) * STAGE;                                     \
        _Pragma("unroll")                                                            \
        for (int i = 0; i < 2; ++i) {                                                \
            int idx = tid + i * 512;                                                 \
            int row = idx >> 3, c4 = idx & 7;                                        \
            float4 v = areg[i];                                                      \
            uint32_t off = (uint32_t)row * ROWB + (uint32_t)c4 * 8u;                 \
            *(uint2*)(sb + T_A + off) = make_uint2(pack_h2(v.x, v.y), pack_h2(v.z, v.w)); \
        }                                                                            \
    }
#define CPA_B(c, stg)                                                                \
    {                                                                                \
        const int k0 = (c) * BK;                                                     \
        uint32_t sb = sbase + OFF_T + (stg) * STAGE;                                 \
        _Pragma("unroll")                                                            \
        for (int i = 0; i < 2; ++i) {                                                \
            int idx = tid + i * 512;                                                 \
            int row = idx >> 2, c8 = idx & 3;                                        \
            uint32_t off = (uint32_t)row * ROWB + (uint32_t)c8 * 16u;                \
            CP16(sb + T_B + off, (const char*)(g_Wkh + row * K_ + k0 + c8 * 8));     \
        }                                                                            \
        CPCOMMIT();                                                                  \
    }

    // prologue: chunk 0 into stage 0
    LDG_A(0);
    CPA_B(0, 0);
    STS_A(0);
    CPWAIT0();
    __syncthreads();

#pragma unroll 1
    for (int c = 0; c < NC; ++c) {
        const int st = c & 1;
        if (c + 1 < NC) {
            LDG_A(c + 1);
            CPA_B(c + 1, st ^ 1);
        }
        // ---- compute chunk c from stage st ----
        {
            const uint32_t sb = sbase + OFF_T + (uint32_t)st * STAGE;
#pragma unroll
            for (int ks = 0; ks < 2; ++ks) {
                uint32_t ah[2][4];
                const uint32_t aoff = sb + T_A + aWarp + fragLane + (uint32_t)ks * 32u;
#pragma unroll
                for (int mt = 0; mt < 2; ++mt)
                    ldm_x4(ah[mt], aoff + (uint32_t)mt * (16u * ROWB));
                const uint32_t boff = sb + T_B + bWarp + fragLane + (uint32_t)ks * 32u;
#pragma unroll
                for (int ntp = 0; ntp < 4; ++ntp) {
                    uint32_t bh[4];
                    ldm_x4(bh, boff + (uint32_t)ntp * (16u * ROWB));
                    // 4 independent accumulators: RAW distance 4
                    mma16816(acc[0][ntp * 2],     ah[0], bh[0], bh[2]);
                    mma16816(acc[1][ntp * 2],     ah[1], bh[0], bh[2]);
                    mma16816(acc[0][ntp * 2 + 1], ah[0], bh[1], bh[3]);
                    mma16816(acc[1][ntp * 2 + 1], ah[1], bh[1], bh[3]);
                }
            }
        }
        if (c + 1 < NC) {
            STS_A((c + 1) & 1);
            CPWAIT0();
            __syncthreads();
        }
    }

    // ---- epilogue: tanh(h + c) dot Wo, reduce ----
    {
        const float* sC = (const float*)(smem + OFF_C);
        const float* sW = (const float*)(smem + OFF_WO);
        float* red = (float*)(smem + OFF_RED);
        __syncthreads();
#pragma unroll
        for (int mt = 0; mt < 2; ++mt) {
            float sl = 0.f, sh = 0.f;
#pragma unroll
            for (int nt = 0; nt < 8; ++nt) {
                int h0 = nw * 64 + nt * 8 + (lane & 3) * 2;
                float c0 = sC[h0], c1 = sC[h0 + 1];
                float w0 = sW[h0], w1 = sW[h0 + 1];
                // fast tanh: sign(x) * (1 - 2/(exp(2|x|)+1))
#define FTANH(x) ({ float _x = (x); float _a = fabsf(_x);                        \
                    float _t = 1.f - __fdividef(2.f, __expf(_a + _a) + 1.f);     \
                    copysignf(_t, _x); })
                sl = fmaf(FTANH(acc[mt][nt][0] + c0), w0, sl);
                sl = fmaf(FTANH(acc[mt][nt][1] + c1), w1, sl);
                sh = fmaf(FTANH(acc[mt][nt][2] + c0), w0, sh);
                sh = fmaf(FTANH(acc[mt][nt][3] + c1), w1, sh);
#undef FTANH
            }
            sl += __shfl_xor_sync(0xffffffffu, sl, 1);
            sl += __shfl_xor_sync(0xffffffffu, sl, 2);
            sh += __shfl_xor_sync(0xffffffffu, sh, 1);
            sh += __shfl_xor_sync(0xffffffffu, sh, 2);
            if ((lane & 3) == 0) {
                int r = mw * 32 + mt * 16 + (lane >> 2);
                red[r * 4 + nw]       = sl;
                red[(r + 8) * 4 + nw] = sh;
            }
        }
        __syncthreads();
        if (tid < MT) {
            float s = red[tid * 4] + red[tid * 4 + 1] + red[tid * 4 + 2] + red[tid * 4 + 3];
            g_logit[b * S_ + s0 + tid] = s;  // bo omitted: softmax shift-invariant
        }
    }
}

// ---------------- 3. softmax over S per batch -> p ----------------
__global__ void softmax_kernel(float* __restrict__ p_out) {
    __shared__ float sred[8];
    __shared__ float sbcast;
    const int b = blockIdx.x, tid = threadIdx.x;

    float mx = -1e30f;
    for (int s = tid; s < S_; s += 256) mx = fmaxf(mx, g_logit[b * S_ + s]);
#pragma unroll
    for (int o = 16; o; o >>= 1) mx = fmaxf(mx, __shfl_xor_sync(0xffffffffu, mx, o));
    if ((tid & 31) == 0) sred[tid >> 5] = mx;
    __syncthreads();
    if (tid < 32) {
        float v = (tid < 8) ? sred[tid] : -1e30f;
#pragma unroll
        for (int o = 4; o; o >>= 1) v = fmaxf(v, __shfl_xor_sync(0xffffffffu, v, o));
        if (tid == 0) sbcast = v;
    }
    __syncthreads();
    mx = sbcast;
    __syncthreads();

    float sum = 0.f;
    for (int s = tid; s < S_; s += 256) {
        float e = expf(g_logit[b * S_ + s] - mx);
        g_logit[b * S_ + s] = e;
        sum += e;
    }
#pragma unroll
    for (int o = 16; o; o >>= 1) sum += __shfl_xor_sync(0xffffffffu, sum, o);
    if ((tid & 31) == 0) sred[tid >> 5] = sum;
    __syncthreads();
    if (tid < 32) {
        float v = (tid < 8) ? sred[tid] : 0.f;
#pragma unroll
        for (int o = 4; o; o >>= 1) v += __shfl_xor_sync(0xffffffffu, v, o);
        if (tid == 0) sbcast = v;
    }
    __syncthreads();
    float inv = 1.f / sbcast;
    for (int s = tid; s < S_; s += 256) p_out[b * S_ + s] = g_logit[b * S_ + s] * inv;
}

// ---------------- 4. out[b,:] = sum_s p[b,s] * v[s,b,:] ----------------
__global__ void wsum_kernel(const float* __restrict__ v, const float* __restrict__ p) {
    const int b = blockIdx.y, sp = blockIdx.x, tid = threadIdx.x;
    const int col = tid * 2;
    const int SCH = S_ / NSPLIT;
    const int s0 = sp * SCH;
    const float* pb = p + b * S_;
    float2 acc = make_float2(0.f, 0.f);
#pragma unroll 4
    for (int i = 0; i < SCH; i++) {
        int s = s0 + i;
        float pv = __ldg(pb + s);
        float2 vv = *(const float2*)(v + ((size_t)s * B_ + b) * V_ + col);
        acc.x = fmaf(pv, vv.x, acc.x);
        acc.y = fmaf(pv, vv.y, acc.y);
    }
    float* dst = g_part + (b * NSPLIT + sp) * V_ + col;
    dst[0] = acc.x;
    dst[1] = acc.y;
}

__global__ void reduce_out(float* __restrict__ out) {
    const int b = blockIdx.x, tid = threadIdx.x;
    float s = 0.f;
#pragma unroll
    for (int i = 0; i < NSPLIT; i++) s += g_part[(b * NSPLIT + i) * V_ + tid];
    out[b * V_ + tid] = s;
}

// ---------------- launch ----------------
extern "C" void kernel_launch(void* const* d_in, const int* in_sizes, int n_in,
                              void* d_out, int out_size) {
    const float* q  = (const float*)d_in[0];
    const float* k  = (const float*)d_in[1];
    const float* v  = (const float*)d_in[2];
    const float* Wk = (const float*)d_in[3];
    const float* bk = (const float*)d_in[4];
    const float* Wq = (const float*)d_in[5];
    const float* bq = (const float*)d_in[6];
    const float* Wo = (const float*)d_in[7];
    // d_in[8] = bo: irrelevant under softmax shift invariance

    float* out = (float*)d_out;    // out[1,B,V]
    float* p   = out + B_ * V_;    // p[B,S]

    cudaFuncSetAttribute(logit_kernel, cudaFuncAttributeMaxDynamicSharedMemorySize, SMEM_TOTAL);

    prep_wk<<<(H_ * K_ + 255) / 256, 256>>>(Wk);
    hq_kernel<<<B_, H_>>>(q, Wq, bq, bk);
    logit_kernel<<<dim3(S_ / MT, B_), THREADS, SMEM_TOTAL>>>(k, Wo);
    softmax_kernel<<<B_, 256>>>(p);
    wsum_kernel<<<dim3(NSPLIT, B_), 256>>>(v, p);
    reduce_out<<<B_, V_>>>(out);
}

// round 14
// speedup vs baseline: 2.3772x; 1.0130x over previous
#include <cuda_runtime.h>
#include <cuda_fp16.h>
#include <cstdint>

#define B_ 32
#define S_ 2048
#define K_ 512
#define V_ 512
#define H_ 256
#define NSPLIT 16

// ---------------- device scratch (allocation-free contract) ----------------
__device__ float g_c[B_ * H_];               // bk + bq + q@Wq.T per (b,h)
__device__ float g_logit[B_ * S_];
__device__ float g_part[B_ * NSPLIT * V_];
__device__ __align__(16) __half g_Wkh[H_ * K_];   // Wk fp16, [H][K] k-major

// ---------------- helpers ----------------
static __device__ __forceinline__ uint32_t smem_u32(const void* p) {
    uint32_t a;
    asm("{ .reg .u64 t; cvta.to.shared.u64 t, %1; cvt.u32.u64 %0, t; }" : "=r"(a) : "l"(p));
    return a;
}
static __device__ __forceinline__ uint32_t pack_h2(float x, float y) {
    __half2 h = __floats2half2_rn(x, y);
    return *reinterpret_cast<uint32_t*>(&h);
}
static __device__ __forceinline__ void ldm_x4(uint32_t* r, uint32_t addr) {
    asm volatile("ldmatrix.sync.aligned.m8n8.x4.shared.b16 {%0,%1,%2,%3}, [%4];"
                 : "=r"(r[0]), "=r"(r[1]), "=r"(r[2]), "=r"(r[3]) : "r"(addr));
}
static __device__ __forceinline__ void mma16816(float* d, const uint32_t* a,
                                                uint32_t b0, uint32_t b1) {
    asm volatile(
        "mma.sync.aligned.m16n8k16.row.col.f32.f16.f16.f32 "
        "{%0,%1,%2,%3}, {%4,%5,%6,%7}, {%8,%9}, {%0,%1,%2,%3};"
        : "+f"(d[0]), "+f"(d[1]), "+f"(d[2]), "+f"(d[3])
        : "r"(a[0]), "r"(a[1]), "r"(a[2]), "r"(a[3]), "r"(b0), "r"(b1));
}
#define CP16(dst, src) \
    asm volatile("cp.async.cg.shared.global [%0], [%1], 16;" :: "r"(dst), "l"(src) : "memory")
#define CPCOMMIT() asm volatile("cp.async.commit_group;" ::: "memory")
#define CPWAIT0()  asm volatile("cp.async.wait_group 0;" ::: "memory")

// ---------------- 0. convert Wk fp32 -> fp16, K-major as-is ----------------
__global__ void prep_wk(const float* __restrict__ Wk) {
    int idx = blockIdx.x * 256 + threadIdx.x;
    if (idx < H_ * K_) g_Wkh[idx] = __float2half_rn(Wk[idx]);
}

// ---------------- 1. c[b,h] = bk[h] + bq[h] + q[b]·Wq[h] ----------------
__global__ void hq_kernel(const float* __restrict__ q, const float* __restrict__ Wq,
                          const float* __restrict__ bq, const float* __restrict__ bk) {
    __shared__ float sq[K_];
    int b = blockIdx.x, h = threadIdx.x;
    for (int i = h; i < K_; i += H_) sq[i] = q[b * K_ + i];
    __syncthreads();
    const float* w = Wq + h * K_;
    float acc = 0.f;
#pragma unroll 8
    for (int kk = 0; kk < K_; kk++) acc = fmaf(sq[kk], w[kk], acc);
    g_c[b * H_ + h] = acc + bq[h] + bk[h];
}

// ---------------- 2. single-pass fp16 HMMA GEMM + fused tanh/Wo epilogue ----------
// CTA: M=64 (one b, 64 s) x N=256 (all H). K chunks of 32, double-buffered.
// 8 warps as 2(M) x 4(N); warp tile 32x64; acc fp32 in registers.
// 2 CTAs/SM: sync/epilogue bubbles of one CTA hide under the other's mma stream.
#define MT 64
#define BK 32
#define NC (K_ / BK)       // 16 chunks
#define THREADS 256
#define ROWB 80            // padded row: 32 fp16 = 64 B data + 16 B pad

#define OFF_C   0
#define OFF_WO  1024
#define OFF_RED 2048
#define OFF_T   4096
#define T_A  0
#define T_B  5120          // A tile: 64 rows * 80 B
#define STAGE 25600        // A (5120) + B (256*80 = 20480)
#define SMEM_TOTAL (OFF_T + 2 * STAGE)   // 55296 B -> 2 CTAs/SM

__global__ void __launch_bounds__(THREADS, 2) logit_kernel(const float* __restrict__ kten,
                                                           const float* __restrict__ Wo) {
    extern __shared__ char smem[];
    const uint32_t sbase = smem_u32(smem);
    const int tid  = threadIdx.x;
    const int wid  = tid >> 5;
    const int lane = tid & 31;
    const int mw = wid >> 2;      // 0..1 (M groups of 32 rows)
    const int nw = wid & 3;       // 0..3 (N groups of 64 cols)
    const int b  = blockIdx.y;
    const int s0 = blockIdx.x * MT;

    if (tid < H_) {
        ((float*)(smem + OFF_C))[tid]  = g_c[b * H_ + tid];
        ((float*)(smem + OFF_WO))[tid] = Wo[tid];
    }

    const float* abase = kten + ((size_t)s0 * B_ + b) * K_;  // row stride B_*K_

    // ldmatrix lane addressing (bytes). Non-trans for BOTH A and B:
    // regs: r0 = rows0-7/k0-7, r1 = rows8-15/k0-7, r2 = rows0-7/k8-15, r3 = rows8-15/k8-15
    const uint32_t fragLane = (uint32_t)(lane & 15) * ROWB + (uint32_t)(lane >> 4) * 16u;
    const uint32_t aWarp = (uint32_t)mw * 32u * ROWB;
    const uint32_t bWarp = (uint32_t)nw * 64u * ROWB;

    float acc[2][8][4];
#pragma unroll
    for (int mt = 0; mt < 2; ++mt)
#pragma unroll
        for (int nt = 0; nt < 8; ++nt)
#pragma unroll
            for (int r = 0; r < 4; ++r) acc[mt][nt][r] = 0.f;

    float4 areg[2];   // 64 rows * 8 float4 = 512 float4; 256 thr -> 2 each

    // ---- loaders (macros over locals) ----
#define LDG_A(c)                                                                     \
    {                                                                                \
        const int k0 = (c) * BK;                                                     \
        _Pragma("unroll")                                                            \
        for (int i = 0; i < 2; ++i) {                                                \
            int idx = tid + i * 256;                                                 \
            int row = idx >> 3, c4 = idx & 7;                                        \
            areg[i] = *(const float4*)(abase + (size_t)row * (B_ * K_) + k0 + c4 * 4); \
        }                                                                            \
    }
#define STS_A(stg)                                                                   \
    {                                                                                \
        char* sb = smem + OFF_T + (stg) * STAGE;                                     \
        _Pragma("unroll")                                                            \
        for (int i = 0; i < 2; ++i) {                                                \
            int idx = tid + i * 256;                                                 \
            int row = idx >> 3, c4 = idx & 7;                                        \
            float4 v = areg[i];                                                      \
            uint32_t off = (uint32_t)row * ROWB + (uint32_t)c4 * 8u;                 \
            *(uint2*)(sb + T_A + off) = make_uint2(pack_h2(v.x, v.y), pack_h2(v.z, v.w)); \
        }                                                                            \
    }
#define CPA_B(c, stg)                                                                \
    {                                                                                \
        const int k0 = (c) * BK;                                                     \
        uint32_t sb = sbase + OFF_T + (stg) * STAGE;                                 \
        _Pragma("unroll")                                                            \
        for (int i = 0; i < 4; ++i) {                                                \
            int idx = tid + i * 256;                                                 \
            int row = idx >> 2, c8 = idx & 3;                                        \
            uint32_t off = (uint32_t)row * ROWB + (uint32_t)c8 * 16u;                \
            CP16(sb + T_B + off, (const char*)(g_Wkh + row * K_ + k0 + c8 * 8));     \
        }                                                                            \
        CPCOMMIT();                                                                  \
    }

    // prologue: chunk 0 into stage 0
    LDG_A(0);
    CPA_B(0, 0);
    STS_A(0);
    CPWAIT0();
    __syncthreads();

#pragma unroll 1
    for (int c = 0; c < NC; ++c) {
        const int st = c & 1;
        if (c + 1 < NC) {
            LDG_A(c + 1);
            CPA_B(c + 1, st ^ 1);
        }
        // ---- compute chunk c from stage st ----
        {
            const uint32_t sb = sbase + OFF_T + (uint32_t)st * STAGE;
#pragma unroll
            for (int ks = 0; ks < 2; ++ks) {
                uint32_t ah[2][4];
                const uint32_t aoff = sb + T_A + aWarp + fragLane + (uint32_t)ks * 32u;
#pragma unroll
                for (int mt = 0; mt < 2; ++mt)
                    ldm_x4(ah[mt], aoff + (uint32_t)mt * (16u * ROWB));
                const uint32_t boff = sb + T_B + bWarp + fragLane + (uint32_t)ks * 32u;
#pragma unroll
                for (int ntp = 0; ntp < 4; ++ntp) {
                    uint32_t bh[4];
                    ldm_x4(bh, boff + (uint32_t)ntp * (16u * ROWB));
                    // 4 independent accumulators: RAW distance 4
                    mma16816(acc[0][ntp * 2],     ah[0], bh[0], bh[2]);
                    mma16816(acc[1][ntp * 2],     ah[1], bh[0], bh[2]);
                    mma16816(acc[0][ntp * 2 + 1], ah[0], bh[1], bh[3]);
                    mma16816(acc[1][ntp * 2 + 1], ah[1], bh[1], bh[3]);
                }
            }
        }
        if (c + 1 < NC) {
            STS_A((c + 1) & 1);
            CPWAIT0();
            __syncthreads();
        }
    }

    // ---- epilogue: tanh(h + c) dot Wo, reduce ----
    {
        const float* sC = (const float*)(smem + OFF_C);
        const float* sW = (const float*)(smem + OFF_WO);
        float* red = (float*)(smem + OFF_RED);
        __syncthreads();
#pragma unroll
        for (int mt = 0; mt < 2; ++mt) {
            float sl = 0.f, sh = 0.f;
#pragma unroll
            for (int nt = 0; nt < 8; ++nt) {
                int h0 = nw * 64 + nt * 8 + (lane & 3) * 2;
                float c0 = sC[h0], c1 = sC[h0 + 1];
                float w0 = sW[h0], w1 = sW[h0 + 1];
                // fast tanh: sign(x) * (1 - 2/(exp(2|x|)+1))
#define FTANH(x) ({ float _x = (x); float _a = fabsf(_x);                        \
                    float _t = 1.f - __fdividef(2.f, __expf(_a + _a) + 1.f);     \
                    copysignf(_t, _x); })
                sl = fmaf(FTANH(acc[mt][nt][0] + c0), w0, sl);
                sl = fmaf(FTANH(acc[mt][nt][1] + c1), w1, sl);
                sh = fmaf(FTANH(acc[mt][nt][2] + c0), w0, sh);
                sh = fmaf(FTANH(acc[mt][nt][3] + c1), w1, sh);
#undef FTANH
            }
            sl += __shfl_xor_sync(0xffffffffu, sl, 1);
            sl += __shfl_xor_sync(0xffffffffu, sl, 2);
            sh += __shfl_xor_sync(0xffffffffu, sh, 1);
            sh += __shfl_xor_sync(0xffffffffu, sh, 2);
            if ((lane & 3) == 0) {
                int r = mw * 32 + mt * 16 + (lane >> 2);
                red[r * 4 + nw]       = sl;
                red[(r + 8) * 4 + nw] = sh;
            }
        }
        __syncthreads();
        if (tid < MT) {
            float s = red[tid * 4] + red[tid * 4 + 1] + red[tid * 4 + 2] + red[tid * 4 + 3];
            g_logit[b * S_ + s0 + tid] = s;  // bo omitted: softmax shift-invariant
        }
    }
}

// ---------------- 3. softmax over S per batch -> p ----------------
__global__ void softmax_kernel(float* __restrict__ p_out) {
    __shared__ float sred[8];
    __shared__ float sbcast;
    const int b = blockIdx.x, tid = threadIdx.x;

    float mx = -1e30f;
    for (int s = tid; s < S_; s += 256) mx = fmaxf(mx, g_logit[b * S_ + s]);
#pragma unroll
    for (int o = 16; o; o >>= 1) mx = fmaxf(mx, __shfl_xor_sync(0xffffffffu, mx, o));
    if ((tid & 31) == 0) sred[tid >> 5] = mx;
    __syncthreads();
    if (tid < 32) {
        float v = (tid < 8) ? sred[tid] : -1e30f;
#pragma unroll
        for (int o = 4; o; o >>= 1) v = fmaxf(v, __shfl_xor_sync(0xffffffffu, v, o));
        if (tid == 0) sbcast = v;
    }
    __syncthreads();
    mx = sbcast;
    __syncthreads();

    float sum = 0.f;
    for (int s = tid; s < S_; s += 256) {
        float e = expf(g_logit[b * S_ + s] - mx);
        g_logit[b * S_ + s] = e;
        sum += e;
    }
#pragma unroll
    for (int o = 16; o; o >>= 1) sum += __shfl_xor_sync(0xffffffffu, sum, o);
    if ((tid & 31) == 0) sred[tid >> 5] = sum;
    __syncthreads();
    if (tid < 32) {
        float v = (tid < 8) ? sred[tid] : 0.f;
#pragma unroll
        for (int o = 4; o; o >>= 1) v += __shfl_xor_sync(0xffffffffu, v, o);
        if (tid == 0) sbcast = v;
    }
    __syncthreads();
    float inv = 1.f / sbcast;
    for (int s = tid; s < S_; s += 256) p_out[b * S_ + s] = g_logit[b * S_ + s] * inv;
}

// ---------------- 4. out[b,:] = sum_s p[b,s] * v[s,b,:] ----------------
__global__ void wsum_kernel(const float* __restrict__ v, const float* __restrict__ p) {
    const int b = blockIdx.y, sp = blockIdx.x, tid = threadIdx.x;
    const int col = tid * 2;
    const int SCH = S_ / NSPLIT;
    const int s0 = sp * SCH;
    const float* pb = p + b * S_;
    float2 acc = make_float2(0.f, 0.f);
#pragma unroll 4
    for (int i = 0; i < SCH; i++) {
        int s = s0 + i;
        float pv = __ldg(pb + s);
        float2 vv = *(const float2*)(v + ((size_t)s * B_ + b) * V_ + col);
        acc.x = fmaf(pv, vv.x, acc.x);
        acc.y = fmaf(pv, vv.y, acc.y);
    }
    float* dst = g_part + (b * NSPLIT + sp) * V_ + col;
    dst[0] = acc.x;
    dst[1] = acc.y;
}

__global__ void reduce_out(float* __restrict__ out) {
    const int b = blockIdx.x, tid = threadIdx.x;
    float s = 0.f;
#pragma unroll
    for (int i = 0; i < NSPLIT; i++) s += g_part[(b * NSPLIT + i) * V_ + tid];
    out[b * V_ + tid] = s;
}

// ---------------- launch ----------------
extern "C" void kernel_launch(void* const* d_in, const int* in_sizes, int n_in,
                              void* d_out, int out_size) {
    const float* q  = (const float*)d_in[0];
    const float* k  = (const float*)d_in[1];
    const float* v  = (const float*)d_in[2];
    const float* Wk = (const float*)d_in[3];
    const float* bk = (const float*)d_in[4];
    const float* Wq = (const float*)d_in[5];
    const float* bq = (const float*)d_in[6];
    const float* Wo = (const float*)d_in[7];
    // d_in[8] = bo: irrelevant under softmax shift invariance

    float* out = (float*)d_out;    // out[1,B,V]
    float* p   = out + B_ * V_;    // p[B,S]

    cudaFuncSetAttribute(logit_kernel, cudaFuncAttributeMaxDynamicSharedMemorySize, SMEM_TOTAL);

    prep_wk<<<(H_ * K_ + 255) / 256, 256>>>(Wk);
    hq_kernel<<<B_, H_>>>(q, Wq, bq, bk);
    logit_kernel<<<dim3(S_ / MT, B_), THREADS, SMEM_TOTAL>>>(k, Wo);
    softmax_kernel<<<B_, 256>>>(p);
    wsum_kernel<<<dim3(NSPLIT, B_), 256>>>(v, p);
    reduce_out<<<B_, V_>>>(out);
}